// round 3
// baseline (speedup 1.0000x reference)
#include <cuda_runtime.h>
#include <cuda_bf16.h>
#include <math.h>

// ---------------------------------------------------------------------------
// Handwriting synthesis network (Graves attention, 3x LSTM-512, GMM head)
// B=64 T=800 U=100 V=80 H=512 KA=10 KO=20
// Persistent-scan architecture: 3 resident kernels (one per LSTM layer) with
// software grid barriers; batched input projections + FC as SIMT GEMMs.
// ---------------------------------------------------------------------------

#define Bn   64
#define Tn   800
#define Un   100
#define Vn   80
#define Hn   512
#define KAn  10
#define Gn   2048          // 4*H
#define K1   595           // 3+V+H
#define K1P  608           // padded
#define FCK  1536          // 3*H
#define OUTC 121

// -------------------- static device scratch --------------------------------
__device__ float g_h0[(size_t)Tn*Bn*Hn];
__device__ float g_h1[(size_t)Tn*Bn*Hn];
__device__ float g_h2[(size_t)Tn*Bn*Hn];
__device__ float g_w [(size_t)Tn*Bn*Vn];
__device__ float g_kap[Bn*KAn];
__device__ float g_WhT0[(size_t)Hn*Gn];
__device__ float g_WhT1[(size_t)Hn*Gn];
__device__ float g_WhT2[(size_t)Hn*Gn];
__device__ float g_WxT0[(size_t)96*Gn];       // W_ih0^T padded 83->96
__device__ float g_cat[(size_t)Tn*Bn*K1P];
__device__ float g_pre[(size_t)Tn*Bn*Gn];
__device__ float g_fcraw[(size_t)Tn*Bn*OUTC];

// barrier state: two independent groups (one per b-tile), padded apart
__device__ volatile unsigned g_barc[64];   // use [0] and [32]
__device__ volatile unsigned g_barg[64];

__device__ __forceinline__ float sigf(float x) { return 1.f/(1.f+expf(-x)); }

// 64-block sense-reversal barrier for group grp (0/1). All 64 blocks of the
// group must call it. threadIdx.x==0 runs the protocol.
__device__ __forceinline__ void grid_bar(int grp)
{
    __threadfence();
    __syncthreads();
    if (threadIdx.x == 0) {
        int s = grp * 32;
        unsigned gen = g_barg[s];
        if (atomicAdd((unsigned*)&g_barc[s], 1u) == 63u) {
            g_barc[s] = 0;
            __threadfence();
            g_barg[s] = gen + 1u;
        } else {
            while (g_barg[s] == gen) __nanosleep(32);
        }
        __threadfence();
    }
    __syncthreads();
}

// -------------------- prep kernels ------------------------------------------
__global__ void k_transpose_whh(const float* __restrict__ W, int layer)
{
    int idx = blockIdx.x * 256 + threadIdx.x;      // over 512*2048
    if (idx >= Hn*Gn) return;
    int k = idx >> 11, j = idx & 2047;
    float v = W[(size_t)j*Hn + k];
    if (layer == 0) g_WhT0[idx] = v;
    else if (layer == 1) g_WhT1[idx] = v;
    else g_WhT2[idx] = v;
}

__global__ void k_build_wxT0(const float* __restrict__ Wih0)
{
    int idx = blockIdx.x * 256 + threadIdx.x;      // over 96*2048
    if (idx >= 96*Gn) return;
    int k = idx >> 11, j = idx & 2047;
    g_WxT0[idx] = (k < 83) ? Wih0[(size_t)j*83 + k] : 0.f;
}

// -------------------- persistent scan: layer 0 + attention -------------------
// grid 128 = (bt 0..1) * 64 + (ht 0..63). block 128 threads.
// block owns h-units [ht*8, ht*8+8) x batch [bt*32, bt*32+32), all 4 gates.
// thread: u = tid&7 (unit), bg = tid>>3 (pair of batches).
// smem: ws[512][32] whh slice | ws0[96][32] wih0 slice | xs[32][100] | hs[32][516]

#define WS_F   (512*32)
#define WS0_F  (96*32)
#define XS_F   (32*100)
#define HS_F   (32*516)

__device__ __forceinline__ void attn_step(
    int t, int b, const float* __restrict__ W_att, const float* __restrict__ b_att,
    const int* __restrict__ chars, const float* __restrict__ cmask, float* sc)
{
    // sc: >= 240 floats of shared scratch
    float* red = sc;          // 128
    float* abk = sc + 128;    // 30 (alpha|beta|kappa)
    float* wsh = sc + 160;    // 80
    const int tid = threadIdx.x;
    const float* h0 = &g_h0[((size_t)t*Bn + b)*Hn];

    int r = tid & 31, q = tid >> 5;
    float s = 0.f;
    if (r < 30) {
        const float* wr = &W_att[(size_t)r*Hn + q*128];
        const float* hh = &h0[q*128];
        #pragma unroll 8
        for (int k = 0; k < 128; k++) s += hh[k] * wr[k];
    }
    red[tid] = s;
    __syncthreads();
    if (tid < 30)
        abk[tid] = expf(red[tid] + red[tid+32] + red[tid+64] + red[tid+96] + b_att[tid]);
    __syncthreads();
    if (tid < 10) {
        float kn = abk[20 + tid] * 0.05f + g_kap[b*KAn + tid];
        g_kap[b*KAn + tid] = kn;
        abk[20 + tid] = kn;
    }
    if (tid < 80) wsh[tid] = 0.f;
    __syncthreads();
    if (tid < 100) {
        float uu = (float)tid;
        float phi = 0.f;
        #pragma unroll
        for (int a = 0; a < 10; a++) {
            float d = abk[20 + a] - uu;
            phi += abk[a] * expf(-abk[10 + a] * d * d);
        }
        float m = cmask[(size_t)b*Un + tid];
        phi *= m * m;
        atomicAdd(&wsh[chars[(size_t)b*Un + tid]], phi);
    }
    __syncthreads();
    if (tid < 80) g_w[((size_t)t*Bn + b)*Vn + tid] = wsh[tid];
}

__global__ __launch_bounds__(128, 1)
void k_scan0(const float* __restrict__ strokes, const float* __restrict__ b0v,
             const float* __restrict__ W_att, const float* __restrict__ b_att,
             const int* __restrict__ chars, const float* __restrict__ cmask)
{
    extern __shared__ float sm[];
    float* ws  = sm;                          // [k][32]
    float* ws0 = sm + WS_F;                   // [k][32]
    float* xs  = sm + WS_F + WS0_F;           // [32][100]
    float* hs  = sm + WS_F + WS0_F + XS_F;    // [32][516]

    const int bt  = blockIdx.x >> 6;
    const int ht  = blockIdx.x & 63;
    const int tid = threadIdx.x;
    const int u   = tid & 7;
    const int bg  = tid >> 3;                 // 0..15

    // one-time weight slice load
    for (int idx = tid; idx < WS_F; idx += 128) {
        int k = idx >> 5, c = idx & 31;
        int col = (c >> 3)*Hn + ht*8 + (c & 7);
        ws[idx] = g_WhT0[(size_t)k*Gn + col];
    }
    for (int idx = tid; idx < WS0_F; idx += 128) {
        int k = idx >> 5, c = idx & 31;
        int col = (c >> 3)*Hn + ht*8 + (c & 7);
        ws0[idx] = g_WxT0[(size_t)k*Gn + col];
    }
    float bias[4];
    #pragma unroll
    for (int g = 0; g < 4; g++) bias[g] = b0v[g*Hn + ht*8 + u];
    if (ht < 32 && tid < KAn) g_kap[(bt*32 + ht)*KAn + tid] = 0.f;
    float c0 = 0.f, c1 = 0.f;
    __syncthreads();

    for (int t = 0; t < Tn; t++) {
        // stage x = [strokes(3) | w_prev(80) | pad0]
        for (int idx = tid; idx < 32*96; idx += 128) {
            int bl = idx / 96, k = idx - bl*96;
            int b = bt*32 + bl;
            float v = 0.f;
            if (k < 3)                 v = strokes[((size_t)b*Tn + t)*3 + k];
            else if (k < 83 && t > 0)  v = g_w[((size_t)(t-1)*Bn + b)*Vn + (k-3)];
            xs[bl*100 + k] = v;
        }
        // stage h_prev
        if (t > 0) {
            const float* hp = &g_h0[((size_t)(t-1)*Bn + bt*32)*Hn];
            for (int idx = tid*4; idx < 32*512; idx += 512) {
                int bl = idx >> 9, k = idx & 511;
                float4 v = *(const float4*)&hp[(size_t)bl*Hn + k];
                *(float4*)&hs[bl*516 + k] = v;
            }
        }
        __syncthreads();

        float a00 = bias[0], a01 = bias[0];
        float a10 = bias[1], a11 = bias[1];
        float a20 = bias[2], a21 = bias[2];
        float a30 = bias[3], a31 = bias[3];

        // x part (k=96, padded)
        #pragma unroll 4
        for (int k = 0; k < 96; k++) {
            float x0 = xs[(bg*2+0)*100 + k];
            float x1 = xs[(bg*2+1)*100 + k];
            float w0 = ws0[k*32 +      u];
            float w1 = ws0[k*32 +  8 + u];
            float w2 = ws0[k*32 + 16 + u];
            float w3 = ws0[k*32 + 24 + u];
            a00 += x0*w0; a01 += x1*w0;
            a10 += x0*w1; a11 += x1*w1;
            a20 += x0*w2; a21 += x1*w2;
            a30 += x0*w3; a31 += x1*w3;
        }
        // recurrent part
        if (t > 0) {
            #pragma unroll 4
            for (int k = 0; k < 512; k++) {
                float x0 = hs[(bg*2+0)*516 + k];
                float x1 = hs[(bg*2+1)*516 + k];
                float w0 = ws[k*32 +      u];
                float w1 = ws[k*32 +  8 + u];
                float w2 = ws[k*32 + 16 + u];
                float w3 = ws[k*32 + 24 + u];
                a00 += x0*w0; a01 += x1*w0;
                a10 += x0*w1; a11 += x1*w1;
                a20 += x0*w2; a21 += x1*w2;
                a30 += x0*w3; a31 += x1*w3;
            }
        }
        // state update
        {
            int b = bt*32 + bg*2;
            float ig = sigf(a00), fg = sigf(a10), gg = tanhf(a20), og = sigf(a30);
            c0 = fg*c0 + ig*gg;
            g_h0[((size_t)t*Bn + b)*Hn + ht*8 + u] = og * tanhf(c0);
            ig = sigf(a01); fg = sigf(a11); gg = tanhf(a21); og = sigf(a31);
            c1 = fg*c1 + ig*gg;
            g_h0[((size_t)t*Bn + b + 1)*Hn + ht*8 + u] = og * tanhf(c1);
        }
        grid_bar(bt);                         // h0[t] complete for this b-tile

        if (ht < 32)
            attn_step(t, bt*32 + ht, W_att, b_att, chars, cmask, hs);
        grid_bar(bt);                         // w[t] complete for this b-tile
    }
}

// -------------------- persistent scan: layers 1/2 ---------------------------
__global__ __launch_bounds__(128, 1)
void k_scan12(int layer)
{
    extern __shared__ float sm[];
    float* ws = sm;              // [k][32]
    float* hs = sm + WS_F;       // [32][516]

    const float* whT  = (layer == 1) ? g_WhT1 : g_WhT2;
    float*       hseq = (layer == 1) ? g_h1   : g_h2;

    const int bt  = blockIdx.x >> 6;
    const int ht  = blockIdx.x & 63;
    const int tid = threadIdx.x;
    const int u   = tid & 7;
    const int bg  = tid >> 3;

    for (int idx = tid; idx < WS_F; idx += 128) {
        int k = idx >> 5, c = idx & 31;
        int col = (c >> 3)*Hn + ht*8 + (c & 7);
        ws[idx] = whT[(size_t)k*Gn + col];
    }
    float c0 = 0.f, c1 = 0.f;
    __syncthreads();

    for (int t = 0; t < Tn; t++) {
        // acc init from precomputed input projection (bias included)
        const float* pp = &g_pre[(size_t)t*Bn*Gn];
        int bA = bt*32 + bg*2, bB = bA + 1;
        float a00 = pp[(size_t)bA*Gn +        ht*8 + u];
        float a01 = pp[(size_t)bB*Gn +        ht*8 + u];
        float a10 = pp[(size_t)bA*Gn + 512  + ht*8 + u];
        float a11 = pp[(size_t)bB*Gn + 512  + ht*8 + u];
        float a20 = pp[(size_t)bA*Gn + 1024 + ht*8 + u];
        float a21 = pp[(size_t)bB*Gn + 1024 + ht*8 + u];
        float a30 = pp[(size_t)bA*Gn + 1536 + ht*8 + u];
        float a31 = pp[(size_t)bB*Gn + 1536 + ht*8 + u];

        if (t > 0) {
            const float* hp = &hseq[((size_t)(t-1)*Bn + bt*32)*Hn];
            for (int idx = tid*4; idx < 32*512; idx += 512) {
                int bl = idx >> 9, k = idx & 511;
                float4 v = *(const float4*)&hp[(size_t)bl*Hn + k];
                *(float4*)&hs[bl*516 + k] = v;
            }
        }
        __syncthreads();

        if (t > 0) {
            #pragma unroll 4
            for (int k = 0; k < 512; k++) {
                float x0 = hs[(bg*2+0)*516 + k];
                float x1 = hs[(bg*2+1)*516 + k];
                float w0 = ws[k*32 +      u];
                float w1 = ws[k*32 +  8 + u];
                float w2 = ws[k*32 + 16 + u];
                float w3 = ws[k*32 + 24 + u];
                a00 += x0*w0; a01 += x1*w0;
                a10 += x0*w1; a11 += x1*w1;
                a20 += x0*w2; a21 += x1*w2;
                a30 += x0*w3; a31 += x1*w3;
            }
        }
        {
            float ig = sigf(a00), fg = sigf(a10), gg = tanhf(a20), og = sigf(a30);
            c0 = fg*c0 + ig*gg;
            hseq[((size_t)t*Bn + bA)*Hn + ht*8 + u] = og * tanhf(c0);
            ig = sigf(a01); fg = sigf(a11); gg = tanhf(a21); og = sigf(a31);
            c1 = fg*c1 + ig*gg;
            hseq[((size_t)t*Bn + bB)*Hn + ht*8 + u] = og * tanhf(c1);
        }
        grid_bar(bt);
    }
}

// -------------------- cat fill ------------------------------------------------
__global__ void k_fill_cat0(const float* __restrict__ strokes)
{
    size_t idx = (size_t)blockIdx.x * 256 + threadIdx.x;  // over T*B*608
    if (idx >= (size_t)Tn*Bn*K1P) return;
    int k = (int)(idx % K1P);
    size_t n = idx / K1P;
    int t = (int)(n >> 6), b = (int)(n & 63);
    float v = 0.f;
    if (k < 3)        v = strokes[((size_t)b*Tn + t)*3 + k];
    else if (k < 83)  v = g_w[n*Vn + (k-3)];
    else if (k < 595) v = g_h0[n*Hn + (k-83)];
    g_cat[idx] = v;
}

__global__ void k_fill_cat_h1()
{
    size_t idx = (size_t)blockIdx.x * 256 + threadIdx.x;  // over T*B*512
    if (idx >= (size_t)Tn*Bn*Hn) return;
    size_t n = idx >> 9;
    int k = (int)(idx & 511);
    g_cat[n*K1P + 83 + k] = g_h1[idx];
}

// -------------------- batched GEMM: pre = cat @ Wih^T + b -------------------
__global__ __launch_bounds__(256, 2)
void k_gemm_pre(const float* __restrict__ Wih, const float* __restrict__ bias)
{
    const int n0 = blockIdx.x * 64;
    const int j0 = blockIdx.y * 64;
    const int tid = threadIdx.x;
    const int tm = tid >> 4, tn = tid & 15;
    const int mload = tid >> 2;
    const int kq = (tid & 3) * 4;

    __shared__ float As[16][68];
    __shared__ float Bs[16][68];

    float acc[4][4] = {};

    for (int k0 = 0; k0 < K1P; k0 += 16) {
        float4 av = *(const float4*)&g_cat[(size_t)(n0+mload)*K1P + k0 + kq];
        As[kq+0][mload] = av.x; As[kq+1][mload] = av.y;
        As[kq+2][mload] = av.z; As[kq+3][mload] = av.w;

        const float* bptr = &Wih[(size_t)(j0+mload)*K1 + k0 + kq];
        #pragma unroll
        for (int i = 0; i < 4; i++) {
            int k = k0 + kq + i;
            Bs[kq+i][mload] = (k < K1) ? bptr[i] : 0.f;
        }
        __syncthreads();
        #pragma unroll
        for (int kk = 0; kk < 16; kk++) {
            float4 a4 = *(const float4*)&As[kk][tm*4];
            float4 b4 = *(const float4*)&Bs[kk][tn*4];
            acc[0][0] += a4.x*b4.x; acc[0][1] += a4.x*b4.y; acc[0][2] += a4.x*b4.z; acc[0][3] += a4.x*b4.w;
            acc[1][0] += a4.y*b4.x; acc[1][1] += a4.y*b4.y; acc[1][2] += a4.y*b4.z; acc[1][3] += a4.y*b4.w;
            acc[2][0] += a4.z*b4.x; acc[2][1] += a4.z*b4.y; acc[2][2] += a4.z*b4.z; acc[2][3] += a4.z*b4.w;
            acc[3][0] += a4.w*b4.x; acc[3][1] += a4.w*b4.y; acc[3][2] += a4.w*b4.z; acc[3][3] += a4.w*b4.w;
        }
        __syncthreads();
    }

    #pragma unroll
    for (int i = 0; i < 4; i++) {
        int n = n0 + tm*4 + i;
        float* cp = &g_pre[(size_t)n*Gn + j0 + tn*4];
        #pragma unroll
        for (int jj = 0; jj < 4; jj++)
            cp[jj] = acc[i][jj] + bias[j0 + tn*4 + jj];
    }
}

// -------------------- FC GEMM: fcraw = [h0|h1|h2] @ Wfc^T + b ---------------
__global__ __launch_bounds__(256, 2)
void k_gemm_fc(const float* __restrict__ Wfc, const float* __restrict__ bfc)
{
    const int n0 = blockIdx.x * 64;
    const int j0 = blockIdx.y * 64;
    const int tid = threadIdx.x;
    const int tm = tid >> 4, tn = tid & 15;
    const int mload = tid >> 2;
    const int kq = (tid & 3) * 4;

    __shared__ float As[16][68];
    __shared__ float Bs[16][68];

    float acc[4][4] = {};

    for (int k0 = 0; k0 < FCK; k0 += 16) {
        const float* hsrc = (k0 < 512) ? g_h0 : (k0 < 1024) ? g_h1 : g_h2;
        int krel = (k0 & 511) + kq;
        float4 av = *(const float4*)&hsrc[(size_t)(n0+mload)*Hn + krel];
        As[kq+0][mload] = av.x; As[kq+1][mload] = av.y;
        As[kq+2][mload] = av.z; As[kq+3][mload] = av.w;

        int row = j0 + mload;
        if (row < OUTC) {
            const float* bptr = &Wfc[(size_t)row*FCK + k0 + kq];
            Bs[kq+0][mload] = bptr[0]; Bs[kq+1][mload] = bptr[1];
            Bs[kq+2][mload] = bptr[2]; Bs[kq+3][mload] = bptr[3];
        } else {
            Bs[kq+0][mload] = 0.f; Bs[kq+1][mload] = 0.f;
            Bs[kq+2][mload] = 0.f; Bs[kq+3][mload] = 0.f;
        }
        __syncthreads();
        #pragma unroll
        for (int kk = 0; kk < 16; kk++) {
            float4 a4 = *(const float4*)&As[kk][tm*4];
            float4 b4 = *(const float4*)&Bs[kk][tn*4];
            acc[0][0] += a4.x*b4.x; acc[0][1] += a4.x*b4.y; acc[0][2] += a4.x*b4.z; acc[0][3] += a4.x*b4.w;
            acc[1][0] += a4.y*b4.x; acc[1][1] += a4.y*b4.y; acc[1][2] += a4.y*b4.z; acc[1][3] += a4.y*b4.w;
            acc[2][0] += a4.z*b4.x; acc[2][1] += a4.z*b4.y; acc[2][2] += a4.z*b4.z; acc[2][3] += a4.z*b4.w;
            acc[3][0] += a4.w*b4.x; acc[3][1] += a4.w*b4.y; acc[3][2] += a4.w*b4.z; acc[3][3] += a4.w*b4.w;
        }
        __syncthreads();
    }

    #pragma unroll
    for (int i = 0; i < 4; i++) {
        int n = n0 + tm*4 + i;
        #pragma unroll
        for (int jj = 0; jj < 4; jj++) {
            int jcol = j0 + tn*4 + jj;
            if (jcol < OUTC)
                g_fcraw[(size_t)n*OUTC + jcol] = acc[i][jj] + bfc[jcol];
        }
    }
}

// -------------------- epilogue ------------------------------------------------
__global__ void k_epilogue(float* __restrict__ out)
{
    int n = blockIdx.x * 128 + threadIdx.x;
    if (n >= Tn*Bn) return;
    const float* r = &g_fcraw[(size_t)n*OUTC];
    int t = n >> 6, b = n & 63;
    float* o = &out[((size_t)b*Tn + t)*OUTC];

    float mx = -1e30f;
    #pragma unroll
    for (int k = 0; k < 20; k++) mx = fmaxf(mx, r[80 + k]);
    float se = 0.f;
    #pragma unroll
    for (int k = 0; k < 20; k++) se += expf(r[80 + k] - mx);
    float lse = mx + logf(se);
    #pragma unroll
    for (int k = 0; k < 20; k++) o[k] = r[80 + k] - lse;          // log_pi
    #pragma unroll
    for (int k = 0; k < 40; k++) o[20 + k] = r[k];                // mu
    #pragma unroll
    for (int k = 0; k < 40; k++) o[60 + k] = r[40 + k];           // log_sigma
    #pragma unroll
    for (int k = 0; k < 20; k++) o[100 + k] = tanhf(r[100 + k]);  // rho
    o[120] = 1.f / (1.f + expf(r[120]));                          // sigmoid(-eos)
}

// -------------------- host launch ---------------------------------------------
extern "C" void kernel_launch(void* const* d_in, const int* in_sizes, int n_in,
                              void* d_out, int out_size)
{
    const int*   chars   = (const int*)  d_in[0];
    const float* cmask   = (const float*)d_in[1];
    const float* strokes = (const float*)d_in[2];
    // d_in[3] strokes_mask unused by reference
    const float* W_ih0   = (const float*)d_in[4];
    const float* W_hh0   = (const float*)d_in[5];
    const float* b0      = (const float*)d_in[6];
    const float* W_att   = (const float*)d_in[7];
    const float* b_att   = (const float*)d_in[8];
    const float* W_ih1   = (const float*)d_in[9];
    const float* W_hh1   = (const float*)d_in[10];
    const float* b1      = (const float*)d_in[11];
    const float* W_ih2   = (const float*)d_in[12];
    const float* W_hh2   = (const float*)d_in[13];
    const float* b2      = (const float*)d_in[14];
    const float* W_fc    = (const float*)d_in[15];
    const float* b_fc    = (const float*)d_in[16];
    float* out = (float*)d_out;

    const int SM0  = (WS_F + WS0_F + XS_F + HS_F) * 4;   // 156,672 B
    const int SM12 = (WS_F + HS_F) * 4;                  // 131,584 B
    cudaFuncSetAttribute(k_scan0,  cudaFuncAttributeMaxDynamicSharedMemorySize, SM0);
    cudaFuncSetAttribute(k_scan12, cudaFuncAttributeMaxDynamicSharedMemorySize, SM12);

    // prep
    k_transpose_whh<<<(Hn*Gn + 255)/256, 256>>>(W_hh0, 0);
    k_transpose_whh<<<(Hn*Gn + 255)/256, 256>>>(W_hh1, 1);
    k_transpose_whh<<<(Hn*Gn + 255)/256, 256>>>(W_hh2, 2);
    k_build_wxT0<<<(96*Gn + 255)/256, 256>>>(W_ih0);

    // layer 0 scan (lstm0 + attention), persistent
    k_scan0<<<128, 128, SM0>>>(strokes, b0, W_att, b_att, chars, cmask);

    // layer 1
    {
        size_t tot = (size_t)Tn*Bn*K1P;
        k_fill_cat0<<<(unsigned)((tot + 255)/256), 256>>>(strokes);
    }
    k_gemm_pre<<<dim3(Tn*Bn/64, Gn/64), 256>>>(W_ih1, b1);
    k_scan12<<<128, 128, SM12>>>(1);

    // layer 2
    {
        size_t tot = (size_t)Tn*Bn*Hn;
        k_fill_cat_h1<<<(unsigned)((tot + 255)/256), 256>>>();
    }
    k_gemm_pre<<<dim3(Tn*Bn/64, Gn/64), 256>>>(W_ih2, b2);
    k_scan12<<<128, 128, SM12>>>(2);

    // head
    k_gemm_fc<<<dim3(Tn*Bn/64, 2), 256>>>(W_fc, b_fc);
    k_epilogue<<<(Tn*Bn + 127)/128, 128>>>(out);
}

// round 4
// speedup vs baseline: 1.1141x; 1.1141x over previous
#include <cuda_runtime.h>
#include <cuda_bf16.h>
#include <math.h>

// ---------------------------------------------------------------------------
// Handwriting synthesis network (Graves attention, 3x LSTM-512, GMM head)
// B=64 T=800 U=100 V=80 H=512 KA=10 KO=20
// Persistent scans + f32x2 (FFMA2) packed math everywhere FMA-bound.
// ---------------------------------------------------------------------------

#define Bn   64
#define Tn   800
#define Un   100
#define Vn   80
#define Hn   512
#define KAn  10
#define Gn   2048          // 4*H
#define K1   595           // 3+V+H
#define K1P  608           // padded
#define FCK  1536          // 3*H
#define OUTC 121

// -------------------- f32x2 helpers -----------------------------------------
__device__ __forceinline__ unsigned long long pack2(float x, float y)
{
    unsigned long long r;
    asm("mov.b64 %0, {%1, %2};" : "=l"(r) : "f"(x), "f"(y));
    return r;
}
__device__ __forceinline__ void fma2(unsigned long long& d,
                                     unsigned long long a, unsigned long long b)
{
    asm("fma.rn.f32x2 %0, %1, %2, %0;" : "+l"(d) : "l"(a), "l"(b));
}
__device__ __forceinline__ float2 unpk(unsigned long long v)
{
    float2 f;
    asm("mov.b64 {%0, %1}, %2;" : "=f"(f.x), "=f"(f.y) : "l"(v));
    return f;
}

// -------------------- static device scratch --------------------------------
__device__ float g_h0[(size_t)Tn*Bn*Hn];
__device__ float g_h1[(size_t)Tn*Bn*Hn];
__device__ float g_h2[(size_t)Tn*Bn*Hn];
__device__ float g_w [(size_t)Tn*Bn*Vn];
__device__ float g_kap[Bn*KAn];
// packed weight layouts: [k][ht(64)][u(8)][g(4)]
__device__ float g_Whp0[(size_t)Hn*Gn];
__device__ float g_Whp1[(size_t)Hn*Gn];
__device__ float g_Whp2[(size_t)Hn*Gn];
__device__ float g_Wxp0[(size_t)96*Gn];
__device__ float g_cat[(size_t)Tn*Bn*K1P];
__device__ float g_pre[(size_t)Tn*Bn*Gn];
__device__ float g_fcraw[(size_t)Tn*Bn*OUTC];

// barrier state: two independent groups (one per b-tile), padded apart
__device__ volatile unsigned g_barc[64];   // use [0] and [32]
__device__ volatile unsigned g_barg[64];

__device__ __forceinline__ float sigf(float x) { return 1.f/(1.f+expf(-x)); }

// 64-block sense-reversal barrier for group grp (0/1).
__device__ __forceinline__ void grid_bar(int grp)
{
    __threadfence();
    __syncthreads();
    if (threadIdx.x == 0) {
        int s = grp * 32;
        unsigned gen = g_barg[s];
        if (atomicAdd((unsigned*)&g_barc[s], 1u) == 63u) {
            g_barc[s] = 0;
            __threadfence();
            g_barg[s] = gen + 1u;
        } else {
            while (g_barg[s] == gen) __nanosleep(32);
        }
        __threadfence();
    }
    __syncthreads();
}

// -------------------- prep kernels ------------------------------------------
// out idx = k*2048 + ht*32 + u*4 + g ; src W[(g*512 + ht*8 + u)*512 + k]
__global__ void k_prep_whh(const float* __restrict__ W, int layer)
{
    int idx = blockIdx.x * 256 + threadIdx.x;
    if (idx >= Hn*Gn) return;
    int g  = idx & 3;
    int u  = (idx >> 2) & 7;
    int ht = (idx >> 5) & 63;
    int k  = idx >> 11;
    float v = W[(size_t)(g*Hn + ht*8 + u)*Hn + k];
    if (layer == 0)      g_Whp0[idx] = v;
    else if (layer == 1) g_Whp1[idx] = v;
    else                 g_Whp2[idx] = v;
}

__global__ void k_prep_wx0(const float* __restrict__ Wih0)
{
    int idx = blockIdx.x * 256 + threadIdx.x;
    if (idx >= 96*Gn) return;
    int g  = idx & 3;
    int u  = (idx >> 2) & 7;
    int ht = (idx >> 5) & 63;
    int k  = idx >> 11;
    g_Wxp0[idx] = (k < 83) ? Wih0[(size_t)(g*Hn + ht*8 + u)*83 + k] : 0.f;
}

// -------------------- persistent scan shapes ---------------------------------
// grid 128 = (bt 0..1)*64 + (ht 0..63). block 128 threads.
// thread: u = tid&7 (unit within 8), bg = tid>>3 (pair of batches, 0..15).
#define WS_F   (512*32)
#define WS0_F  (96*32)
#define XS_F   (32*100)
#define HS_F   (32*516)

__device__ __forceinline__ void attn_step(
    int t, int b, const float* __restrict__ W_att, const float* __restrict__ b_att,
    const int* __restrict__ chars, const float* __restrict__ cmask, float* sc)
{
    float* red = sc;          // 128
    float* abk = sc + 128;    // 30
    float* wsh = sc + 160;    // 80
    const int tid = threadIdx.x;
    const float* h0 = &g_h0[((size_t)t*Bn + b)*Hn];

    int r = tid & 31, q = tid >> 5;
    float s = 0.f;
    if (r < 30) {
        const float* wr = &W_att[(size_t)r*Hn + q*128];
        const float* hh = &h0[q*128];
        #pragma unroll 8
        for (int k = 0; k < 128; k++) s += hh[k] * wr[k];
    }
    red[tid] = s;
    __syncthreads();
    if (tid < 30)
        abk[tid] = expf(red[tid] + red[tid+32] + red[tid+64] + red[tid+96] + b_att[tid]);
    __syncthreads();
    if (tid < 10) {
        float kn = abk[20 + tid] * 0.05f + g_kap[b*KAn + tid];
        g_kap[b*KAn + tid] = kn;
        abk[20 + tid] = kn;
    }
    if (tid < 80) wsh[tid] = 0.f;
    __syncthreads();
    if (tid < 100) {
        float uu = (float)tid;
        float phi = 0.f;
        #pragma unroll
        for (int a = 0; a < 10; a++) {
            float d = abk[20 + a] - uu;
            phi += abk[a] * expf(-abk[10 + a] * d * d);
        }
        float m = cmask[(size_t)b*Un + tid];
        phi *= m * m;
        atomicAdd(&wsh[chars[(size_t)b*Un + tid]], phi);
    }
    __syncthreads();
    if (tid < 80) g_w[((size_t)t*Bn + b)*Vn + tid] = wsh[tid];
}

__global__ __launch_bounds__(128, 1)
void k_scan0(const float* __restrict__ strokes, const float* __restrict__ b0v,
             const float* __restrict__ W_att, const float* __restrict__ b_att,
             const int* __restrict__ chars, const float* __restrict__ cmask)
{
    extern __shared__ float sm[];
    float* ws  = sm;                          // [k][32]  (u*4+g packed)
    float* ws0 = sm + WS_F;
    float* xs  = sm + WS_F + WS0_F;           // [32][100]
    float* hs  = sm + WS_F + WS0_F + XS_F;    // [32][516]

    const int bt  = blockIdx.x >> 6;
    const int ht  = blockIdx.x & 63;
    const int tid = threadIdx.x;
    const int u   = tid & 7;
    const int bg  = tid >> 3;                 // 0..15

    // one-time weight slice load (coalesced: 32 consecutive floats per k)
    for (int idx = tid; idx < WS_F; idx += 128)
        ws[idx] = g_Whp0[(size_t)(idx >> 5)*Gn + ht*32 + (idx & 31)];
    for (int idx = tid; idx < WS0_F; idx += 128)
        ws0[idx] = g_Wxp0[(size_t)(idx >> 5)*Gn + ht*32 + (idx & 31)];

    unsigned long long bias01, bias23;
    {
        float bi = b0v[       ht*8 + u];
        float bf = b0v[ Hn  + ht*8 + u];
        float bg2= b0v[2*Hn + ht*8 + u];
        float bo = b0v[3*Hn + ht*8 + u];
        bias01 = pack2(bi, bf);
        bias23 = pack2(bg2, bo);
    }
    if (ht < 32 && tid < KAn) g_kap[(bt*32 + ht)*KAn + tid] = 0.f;
    float cA = 0.f, cB = 0.f;
    __syncthreads();

    const int rA = (bg*2+0)*516, rB = (bg*2+1)*516;
    const int xA0 = (bg*2+0)*100, xB0 = (bg*2+1)*100;
    const ulonglong2* wv  = (const ulonglong2*)ws;   // idx k*8+u
    const ulonglong2* wv0 = (const ulonglong2*)ws0;

    for (int t = 0; t < Tn; t++) {
        // stage x = [strokes(3) | w_prev(80) | pad0]
        for (int idx = tid; idx < 32*96; idx += 128) {
            int bl = idx / 96, k = idx - bl*96;
            int b = bt*32 + bl;
            float v = 0.f;
            if (k < 3)                 v = strokes[((size_t)b*Tn + t)*3 + k];
            else if (k < 83 && t > 0)  v = g_w[((size_t)(t-1)*Bn + b)*Vn + (k-3)];
            xs[bl*100 + k] = v;
        }
        if (t > 0) {
            const float* hp = &g_h0[((size_t)(t-1)*Bn + bt*32)*Hn];
            for (int idx = tid*4; idx < 32*512; idx += 512) {
                int bl = idx >> 9, k = idx & 511;
                float4 v = *(const float4*)&hp[(size_t)bl*Hn + k];
                *(float4*)&hs[bl*516 + k] = v;
            }
        }
        __syncthreads();

        unsigned long long aA01 = bias01, aA23 = bias23;
        unsigned long long aB01 = bias01, aB23 = bias23;

        // x part (k = 96 padded)
        #pragma unroll 8
        for (int k = 0; k < 96; k++) {
            ulonglong2 w = wv0[k*8 + u];
            unsigned long long xa = pack2(xs[xA0 + k], xs[xA0 + k]);
            unsigned long long xb = pack2(xs[xB0 + k], xs[xB0 + k]);
            fma2(aA01, xa, w.x); fma2(aA23, xa, w.y);
            fma2(aB01, xb, w.x); fma2(aB23, xb, w.y);
        }
        // recurrent part
        if (t > 0) {
            #pragma unroll 8
            for (int k = 0; k < 512; k++) {
                ulonglong2 w = wv[k*8 + u];
                unsigned long long xa = pack2(hs[rA + k], hs[rA + k]);
                unsigned long long xb = pack2(hs[rB + k], hs[rB + k]);
                fma2(aA01, xa, w.x); fma2(aA23, xa, w.y);
                fma2(aB01, xb, w.x); fma2(aB23, xb, w.y);
            }
        }
        // state update
        {
            int b = bt*32 + bg*2;
            float2 if_A = unpk(aA01), goA = unpk(aA23);
            float ig = sigf(if_A.x), fg = sigf(if_A.y), gg = tanhf(goA.x), og = sigf(goA.y);
            cA = fg*cA + ig*gg;
            g_h0[((size_t)t*Bn + b)*Hn + ht*8 + u] = og * tanhf(cA);
            float2 if_B = unpk(aB01), goB = unpk(aB23);
            ig = sigf(if_B.x); fg = sigf(if_B.y); gg = tanhf(goB.x); og = sigf(goB.y);
            cB = fg*cB + ig*gg;
            g_h0[((size_t)t*Bn + b + 1)*Hn + ht*8 + u] = og * tanhf(cB);
        }
        grid_bar(bt);                         // h0[t] done for this b-tile

        if (ht < 32)
            attn_step(t, bt*32 + ht, W_att, b_att, chars, cmask, hs);
        grid_bar(bt);                         // w[t] done for this b-tile
    }
}

// -------------------- persistent scan: layers 1/2 ---------------------------
__global__ __launch_bounds__(128, 1)
void k_scan12(int layer)
{
    extern __shared__ float sm[];
    float* ws = sm;              // [k][32]
    float* hs = sm + WS_F;       // [32][516]

    const float* whp  = (layer == 1) ? g_Whp1 : g_Whp2;
    float*       hseq = (layer == 1) ? g_h1   : g_h2;

    const int bt  = blockIdx.x >> 6;
    const int ht  = blockIdx.x & 63;
    const int tid = threadIdx.x;
    const int u   = tid & 7;
    const int bg  = tid >> 3;

    for (int idx = tid; idx < WS_F; idx += 128)
        ws[idx] = whp[(size_t)(idx >> 5)*Gn + ht*32 + (idx & 31)];
    float cA = 0.f, cB = 0.f;
    __syncthreads();

    const int rA = (bg*2+0)*516, rB = (bg*2+1)*516;
    const ulonglong2* wv = (const ulonglong2*)ws;

    for (int t = 0; t < Tn; t++) {
        const float* pp = &g_pre[(size_t)t*Bn*Gn];
        int bA = bt*32 + bg*2, bB = bA + 1;
        unsigned long long aA01 = pack2(pp[(size_t)bA*Gn +        ht*8 + u],
                                        pp[(size_t)bA*Gn + 512  + ht*8 + u]);
        unsigned long long aA23 = pack2(pp[(size_t)bA*Gn + 1024 + ht*8 + u],
                                        pp[(size_t)bA*Gn + 1536 + ht*8 + u]);
        unsigned long long aB01 = pack2(pp[(size_t)bB*Gn +        ht*8 + u],
                                        pp[(size_t)bB*Gn + 512  + ht*8 + u]);
        unsigned long long aB23 = pack2(pp[(size_t)bB*Gn + 1024 + ht*8 + u],
                                        pp[(size_t)bB*Gn + 1536 + ht*8 + u]);

        if (t > 0) {
            const float* hp = &hseq[((size_t)(t-1)*Bn + bt*32)*Hn];
            for (int idx = tid*4; idx < 32*512; idx += 512) {
                int bl = idx >> 9, k = idx & 511;
                float4 v = *(const float4*)&hp[(size_t)bl*Hn + k];
                *(float4*)&hs[bl*516 + k] = v;
            }
        }
        __syncthreads();

        if (t > 0) {
            #pragma unroll 8
            for (int k = 0; k < 512; k++) {
                ulonglong2 w = wv[k*8 + u];
                unsigned long long xa = pack2(hs[rA + k], hs[rA + k]);
                unsigned long long xb = pack2(hs[rB + k], hs[rB + k]);
                fma2(aA01, xa, w.x); fma2(aA23, xa, w.y);
                fma2(aB01, xb, w.x); fma2(aB23, xb, w.y);
            }
        }
        {
            float2 if_A = unpk(aA01), goA = unpk(aA23);
            float ig = sigf(if_A.x), fg = sigf(if_A.y), gg = tanhf(goA.x), og = sigf(goA.y);
            cA = fg*cA + ig*gg;
            hseq[((size_t)t*Bn + bA)*Hn + ht*8 + u] = og * tanhf(cA);
            float2 if_B = unpk(aB01), goB = unpk(aB23);
            ig = sigf(if_B.x); fg = sigf(if_B.y); gg = tanhf(goB.x); og = sigf(goB.y);
            cB = fg*cB + ig*gg;
            hseq[((size_t)t*Bn + bB)*Hn + ht*8 + u] = og * tanhf(cB);
        }
        grid_bar(bt);
    }
}

// -------------------- cat fill ------------------------------------------------
__global__ void k_fill_cat0(const float* __restrict__ strokes)
{
    size_t idx = (size_t)blockIdx.x * 256 + threadIdx.x;  // over T*B*608
    if (idx >= (size_t)Tn*Bn*K1P) return;
    int k = (int)(idx % K1P);
    size_t n = idx / K1P;
    int t = (int)(n >> 6), b = (int)(n & 63);
    float v = 0.f;
    if (k < 3)        v = strokes[((size_t)b*Tn + t)*3 + k];
    else if (k < 83)  v = g_w[n*Vn + (k-3)];
    else if (k < 595) v = g_h0[n*Hn + (k-83)];
    g_cat[idx] = v;
}

__global__ void k_fill_cat_h1()
{
    size_t idx = (size_t)blockIdx.x * 256 + threadIdx.x;  // over T*B*512
    if (idx >= (size_t)Tn*Bn*Hn) return;
    size_t n = idx >> 9;
    int k = (int)(idx & 511);
    g_cat[n*K1P + 83 + k] = g_h1[idx];
}

// -------------------- batched GEMM: pre = cat @ Wih^T + b -------------------
__global__ __launch_bounds__(256, 2)
void k_gemm_pre(const float* __restrict__ Wih, const float* __restrict__ bias)
{
    const int n0 = blockIdx.x * 64;
    const int j0 = blockIdx.y * 64;
    const int tid = threadIdx.x;
    const int tm = tid >> 4, tn = tid & 15;
    const int mload = tid >> 2;
    const int kq = (tid & 3) * 4;

    __shared__ float As[16][68];
    __shared__ float Bs[16][68];

    unsigned long long acc2[4][2];
    #pragma unroll
    for (int i = 0; i < 4; i++) { acc2[i][0] = 0ull; acc2[i][1] = 0ull; }

    for (int k0 = 0; k0 < K1P; k0 += 16) {
        float4 av = *(const float4*)&g_cat[(size_t)(n0+mload)*K1P + k0 + kq];
        As[kq+0][mload] = av.x; As[kq+1][mload] = av.y;
        As[kq+2][mload] = av.z; As[kq+3][mload] = av.w;

        const float* bptr = &Wih[(size_t)(j0+mload)*K1 + k0 + kq];
        #pragma unroll
        for (int i = 0; i < 4; i++) {
            int k = k0 + kq + i;
            Bs[kq+i][mload] = (k < K1) ? bptr[i] : 0.f;
        }
        __syncthreads();
        #pragma unroll
        for (int kk = 0; kk < 16; kk++) {
            float4 a4 = *(const float4*)&As[kk][tm*4];
            ulonglong2 b2 = *(const ulonglong2*)&Bs[kk][tn*4];
            unsigned long long ax;
            ax = pack2(a4.x, a4.x); fma2(acc2[0][0], ax, b2.x); fma2(acc2[0][1], ax, b2.y);
            ax = pack2(a4.y, a4.y); fma2(acc2[1][0], ax, b2.x); fma2(acc2[1][1], ax, b2.y);
            ax = pack2(a4.z, a4.z); fma2(acc2[2][0], ax, b2.x); fma2(acc2[2][1], ax, b2.y);
            ax = pack2(a4.w, a4.w); fma2(acc2[3][0], ax, b2.x); fma2(acc2[3][1], ax, b2.y);
        }
        __syncthreads();
    }

    #pragma unroll
    for (int i = 0; i < 4; i++) {
        int n = n0 + tm*4 + i;
        float* cp = &g_pre[(size_t)n*Gn + j0 + tn*4];
        float2 c01 = unpk(acc2[i][0]);
        float2 c23 = unpk(acc2[i][1]);
        cp[0] = c01.x + bias[j0 + tn*4 + 0];
        cp[1] = c01.y + bias[j0 + tn*4 + 1];
        cp[2] = c23.x + bias[j0 + tn*4 + 2];
        cp[3] = c23.y + bias[j0 + tn*4 + 3];
    }
}

// -------------------- FC GEMM: fcraw = [h0|h1|h2] @ Wfc^T + b ---------------
__global__ __launch_bounds__(256, 2)
void k_gemm_fc(const float* __restrict__ Wfc, const float* __restrict__ bfc)
{
    const int n0 = blockIdx.x * 64;
    const int j0 = blockIdx.y * 64;
    const int tid = threadIdx.x;
    const int tm = tid >> 4, tn = tid & 15;
    const int mload = tid >> 2;
    const int kq = (tid & 3) * 4;

    __shared__ float As[16][68];
    __shared__ float Bs[16][68];

    unsigned long long acc2[4][2];
    #pragma unroll
    for (int i = 0; i < 4; i++) { acc2[i][0] = 0ull; acc2[i][1] = 0ull; }

    for (int k0 = 0; k0 < FCK; k0 += 16) {
        const float* hsrc = (k0 < 512) ? g_h0 : (k0 < 1024) ? g_h1 : g_h2;
        int krel = (k0 & 511) + kq;
        float4 av = *(const float4*)&hsrc[(size_t)(n0+mload)*Hn + krel];
        As[kq+0][mload] = av.x; As[kq+1][mload] = av.y;
        As[kq+2][mload] = av.z; As[kq+3][mload] = av.w;

        int row = j0 + mload;
        if (row < OUTC) {
            const float* bptr = &Wfc[(size_t)row*FCK + k0 + kq];
            Bs[kq+0][mload] = bptr[0]; Bs[kq+1][mload] = bptr[1];
            Bs[kq+2][mload] = bptr[2]; Bs[kq+3][mload] = bptr[3];
        } else {
            Bs[kq+0][mload] = 0.f; Bs[kq+1][mload] = 0.f;
            Bs[kq+2][mload] = 0.f; Bs[kq+3][mload] = 0.f;
        }
        __syncthreads();
        #pragma unroll
        for (int kk = 0; kk < 16; kk++) {
            float4 a4 = *(const float4*)&As[kk][tm*4];
            ulonglong2 b2 = *(const ulonglong2*)&Bs[kk][tn*4];
            unsigned long long ax;
            ax = pack2(a4.x, a4.x); fma2(acc2[0][0], ax, b2.x); fma2(acc2[0][1], ax, b2.y);
            ax = pack2(a4.y, a4.y); fma2(acc2[1][0], ax, b2.x); fma2(acc2[1][1], ax, b2.y);
            ax = pack2(a4.z, a4.z); fma2(acc2[2][0], ax, b2.x); fma2(acc2[2][1], ax, b2.y);
            ax = pack2(a4.w, a4.w); fma2(acc2[3][0], ax, b2.x); fma2(acc2[3][1], ax, b2.y);
        }
        __syncthreads();
    }

    #pragma unroll
    for (int i = 0; i < 4; i++) {
        int n = n0 + tm*4 + i;
        float2 c01 = unpk(acc2[i][0]);
        float2 c23 = unpk(acc2[i][1]);
        float cv[4] = {c01.x, c01.y, c23.x, c23.y};
        #pragma unroll
        for (int jj = 0; jj < 4; jj++) {
            int jcol = j0 + tn*4 + jj;
            if (jcol < OUTC)
                g_fcraw[(size_t)n*OUTC + jcol] = cv[jj] + bfc[jcol];
        }
    }
}

// -------------------- epilogue ------------------------------------------------
__global__ void k_epilogue(float* __restrict__ out)
{
    int n = blockIdx.x * 128 + threadIdx.x;
    if (n >= Tn*Bn) return;
    const float* r = &g_fcraw[(size_t)n*OUTC];
    int t = n >> 6, b = n & 63;
    float* o = &out[((size_t)b*Tn + t)*OUTC];

    float mx = -1e30f;
    #pragma unroll
    for (int k = 0; k < 20; k++) mx = fmaxf(mx, r[80 + k]);
    float se = 0.f;
    #pragma unroll
    for (int k = 0; k < 20; k++) se += expf(r[80 + k] - mx);
    float lse = mx + logf(se);
    #pragma unroll
    for (int k = 0; k < 20; k++) o[k] = r[80 + k] - lse;          // log_pi
    #pragma unroll
    for (int k = 0; k < 40; k++) o[20 + k] = r[k];                // mu
    #pragma unroll
    for (int k = 0; k < 40; k++) o[60 + k] = r[40 + k];           // log_sigma
    #pragma unroll
    for (int k = 0; k < 20; k++) o[100 + k] = tanhf(r[100 + k]);  // rho
    o[120] = 1.f / (1.f + expf(r[120]));                          // sigmoid(-eos)
}

// -------------------- host launch ---------------------------------------------
extern "C" void kernel_launch(void* const* d_in, const int* in_sizes, int n_in,
                              void* d_out, int out_size)
{
    const int*   chars   = (const int*)  d_in[0];
    const float* cmask   = (const float*)d_in[1];
    const float* strokes = (const float*)d_in[2];
    // d_in[3] strokes_mask unused by reference
    const float* W_ih0   = (const float*)d_in[4];
    const float* W_hh0   = (const float*)d_in[5];
    const float* b0      = (const float*)d_in[6];
    const float* W_att   = (const float*)d_in[7];
    const float* b_att   = (const float*)d_in[8];
    const float* W_ih1   = (const float*)d_in[9];
    const float* W_hh1   = (const float*)d_in[10];
    const float* b1      = (const float*)d_in[11];
    const float* W_ih2   = (const float*)d_in[12];
    const float* W_hh2   = (const float*)d_in[13];
    const float* b2      = (const float*)d_in[14];
    const float* W_fc    = (const float*)d_in[15];
    const float* b_fc    = (const float*)d_in[16];
    float* out = (float*)d_out;

    const int SM0  = (WS_F + WS0_F + XS_F + HS_F) * 4;   // 156,672 B
    const int SM12 = (WS_F + HS_F) * 4;                  // 131,584 B
    cudaFuncSetAttribute(k_scan0,  cudaFuncAttributeMaxDynamicSharedMemorySize, SM0);
    cudaFuncSetAttribute(k_scan12, cudaFuncAttributeMaxDynamicSharedMemorySize, SM12);

    // prep: packed weight layouts
    k_prep_whh<<<(Hn*Gn + 255)/256, 256>>>(W_hh0, 0);
    k_prep_whh<<<(Hn*Gn + 255)/256, 256>>>(W_hh1, 1);
    k_prep_whh<<<(Hn*Gn + 255)/256, 256>>>(W_hh2, 2);
    k_prep_wx0<<<(96*Gn + 255)/256, 256>>>(W_ih0);

    // layer 0 scan (lstm0 + attention), persistent
    k_scan0<<<128, 128, SM0>>>(strokes, b0, W_att, b_att, chars, cmask);

    // layer 1
    {
        size_t tot = (size_t)Tn*Bn*K1P;
        k_fill_cat0<<<(unsigned)((tot + 255)/256), 256>>>(strokes);
    }
    k_gemm_pre<<<dim3(Tn*Bn/64, Gn/64), 256>>>(W_ih1, b1);
    k_scan12<<<128, 128, SM12>>>(1);

    // layer 2
    {
        size_t tot = (size_t)Tn*Bn*Hn;
        k_fill_cat_h1<<<(unsigned)((tot + 255)/256), 256>>>();
    }
    k_gemm_pre<<<dim3(Tn*Bn/64, Gn/64), 256>>>(W_ih2, b2);
    k_scan12<<<128, 128, SM12>>>(2);

    // head
    k_gemm_fc<<<dim3(Tn*Bn/64, 2), 256>>>(W_fc, b_fc);
    k_epilogue<<<(Tn*Bn + 127)/128, 128>>>(out);
}

// round 5
// speedup vs baseline: 1.1580x; 1.0394x over previous
#include <cuda_runtime.h>
#include <cuda_bf16.h>
#include <math.h>

// ---------------------------------------------------------------------------
// Handwriting synthesis network (Graves attention, 3x LSTM-512, GMM head)
// B=64 T=800 U=100 V=80 H=512 KA=10 KO=20
// Persistent scans + f32x2 math; fast acquire/release grid barrier (no fences,
// no nanosleep) — cooperative-groups-style protocol.
// ---------------------------------------------------------------------------

#define Bn   64
#define Tn   800
#define Un   100
#define Vn   80
#define Hn   512
#define KAn  10
#define Gn   2048          // 4*H
#define K1   595           // 3+V+H
#define K1P  608           // padded
#define FCK  1536          // 3*H
#define OUTC 121

// -------------------- f32x2 helpers -----------------------------------------
__device__ __forceinline__ unsigned long long pack2(float x, float y)
{
    unsigned long long r;
    asm("mov.b64 %0, {%1, %2};" : "=l"(r) : "f"(x), "f"(y));
    return r;
}
__device__ __forceinline__ void fma2(unsigned long long& d,
                                     unsigned long long a, unsigned long long b)
{
    asm("fma.rn.f32x2 %0, %1, %2, %0;" : "+l"(d) : "l"(a), "l"(b));
}
__device__ __forceinline__ float2 unpk(unsigned long long v)
{
    float2 f;
    asm("mov.b64 {%0, %1}, %2;" : "=f"(f.x), "=f"(f.y) : "l"(v));
    return f;
}

// -------------------- static device scratch --------------------------------
__device__ float g_h0[(size_t)Tn*Bn*Hn];
__device__ float g_h1[(size_t)Tn*Bn*Hn];
__device__ float g_h2[(size_t)Tn*Bn*Hn];
__device__ float g_w [(size_t)Tn*Bn*Vn];
__device__ float g_kap[Bn*KAn];
// packed weight layouts: [k][ht(64)][u(8)][g(4)]
__device__ float g_Whp0[(size_t)Hn*Gn];
__device__ float g_Whp1[(size_t)Hn*Gn];
__device__ float g_Whp2[(size_t)Hn*Gn];
__device__ float g_Wxp0[(size_t)96*Gn];
__device__ float g_cat[(size_t)Tn*Bn*K1P];
__device__ float g_pre[(size_t)Tn*Bn*Gn];
__device__ float g_fcraw[(size_t)Tn*Bn*OUTC];

// barrier state: two independent groups (one per b-tile), padded apart
__device__ unsigned g_barc[64];   // use [0] and [32]
__device__ unsigned g_barg[64];

__device__ __forceinline__ float sigf(float x) { return 1.f/(1.f+expf(-x)); }

// 64-block grid barrier, CG-style: syncthreads gives intra-CTA happens-before,
// arrival is atom.release (orders all the CTA's prior global stores), waiters
// spin on ld.acquire of the generation word. No MEMBARs, no nanosleep.
__device__ __forceinline__ void grid_bar(int grp)
{
    __syncthreads();
    if (threadIdx.x == 0) {
        unsigned* cnt = &g_barc[grp*32];
        unsigned* gen = &g_barg[grp*32];
        unsigned g;
        asm volatile("ld.relaxed.gpu.u32 %0, [%1];" : "=r"(g) : "l"(gen) : "memory");
        unsigned prev;
        asm volatile("atom.release.gpu.add.u32 %0, [%1], 1;"
                     : "=r"(prev) : "l"(cnt) : "memory");
        if (prev == 63u) {
            asm volatile("st.relaxed.gpu.u32 [%0], 0;" :: "l"(cnt) : "memory");
            asm volatile("st.release.gpu.u32 [%0], %1;" :: "l"(gen), "r"(g + 1u) : "memory");
        } else {
            unsigned cur;
            do {
                asm volatile("ld.acquire.gpu.u32 %0, [%1];"
                             : "=r"(cur) : "l"(gen) : "memory");
            } while (cur == g);
        }
    }
    __syncthreads();
}

// -------------------- prep kernels ------------------------------------------
// out idx = k*2048 + ht*32 + u*4 + g ; src W[(g*512 + ht*8 + u)*512 + k]
__global__ void k_prep_whh(const float* __restrict__ W, int layer)
{
    int idx = blockIdx.x * 256 + threadIdx.x;
    if (idx >= Hn*Gn) return;
    int g  = idx & 3;
    int u  = (idx >> 2) & 7;
    int ht = (idx >> 5) & 63;
    int k  = idx >> 11;
    float v = W[(size_t)(g*Hn + ht*8 + u)*Hn + k];
    if (layer == 0)      g_Whp0[idx] = v;
    else if (layer == 1) g_Whp1[idx] = v;
    else                 g_Whp2[idx] = v;
}

__global__ void k_prep_wx0(const float* __restrict__ Wih0)
{
    int idx = blockIdx.x * 256 + threadIdx.x;
    if (idx >= 96*Gn) return;
    int g  = idx & 3;
    int u  = (idx >> 2) & 7;
    int ht = (idx >> 5) & 63;
    int k  = idx >> 11;
    g_Wxp0[idx] = (k < 83) ? Wih0[(size_t)(g*Hn + ht*8 + u)*83 + k] : 0.f;
}

// -------------------- persistent scan shapes ---------------------------------
// grid 128 = (bt 0..1)*64 + (ht 0..63). block 128 threads.
// thread: u = tid&7 (unit within 8), bg = tid>>3 (pair of batches, 0..15).
#define WS_F   (512*32)
#define WS0_F  (96*32)
#define XS_F   (32*100)
#define HS_F   (32*516)

__device__ __forceinline__ void attn_step(
    int t, int b, const float* __restrict__ W_att, const float* __restrict__ b_att,
    const int* __restrict__ chars, const float* __restrict__ cmask, float* sc)
{
    float* red = sc;          // 128
    float* abk = sc + 128;    // 30
    float* wsh = sc + 160;    // 80
    const int tid = threadIdx.x;
    const float* h0 = &g_h0[((size_t)t*Bn + b)*Hn];

    int r = tid & 31, q = tid >> 5;
    float s = 0.f;
    if (r < 30) {
        const float* wr = &W_att[(size_t)r*Hn + q*128];
        const float* hh = &h0[q*128];
        #pragma unroll 8
        for (int k = 0; k < 128; k++) s += hh[k] * wr[k];
    }
    red[tid] = s;
    __syncthreads();
    if (tid < 30)
        abk[tid] = expf(red[tid] + red[tid+32] + red[tid+64] + red[tid+96] + b_att[tid]);
    __syncthreads();
    if (tid < 10) {
        float kn = abk[20 + tid] * 0.05f + g_kap[b*KAn + tid];
        g_kap[b*KAn + tid] = kn;
        abk[20 + tid] = kn;
    }
    if (tid < 80) wsh[tid] = 0.f;
    __syncthreads();
    if (tid < 100) {
        float uu = (float)tid;
        float phi = 0.f;
        #pragma unroll
        for (int a = 0; a < 10; a++) {
            float d = abk[20 + a] - uu;
            phi += abk[a] * expf(-abk[10 + a] * d * d);
        }
        float m = cmask[(size_t)b*Un + tid];
        phi *= m * m;
        atomicAdd(&wsh[chars[(size_t)b*Un + tid]], phi);
    }
    __syncthreads();
    if (tid < 80) g_w[((size_t)t*Bn + b)*Vn + tid] = wsh[tid];
}

__global__ __launch_bounds__(128, 1)
void k_scan0(const float* __restrict__ strokes, const float* __restrict__ b0v,
             const float* __restrict__ W_att, const float* __restrict__ b_att,
             const int* __restrict__ chars, const float* __restrict__ cmask)
{
    extern __shared__ float sm[];
    float* ws  = sm;                          // [k][32]  (u*4+g packed)
    float* ws0 = sm + WS_F;
    float* xs  = sm + WS_F + WS0_F;           // [32][100]
    float* hs  = sm + WS_F + WS0_F + XS_F;    // [32][516]

    const int bt  = blockIdx.x >> 6;
    const int ht  = blockIdx.x & 63;
    const int tid = threadIdx.x;
    const int u   = tid & 7;
    const int bg  = tid >> 3;                 // 0..15

    // one-time weight slice load (coalesced: 32 consecutive floats per k)
    for (int idx = tid; idx < WS_F; idx += 128)
        ws[idx] = g_Whp0[(size_t)(idx >> 5)*Gn + ht*32 + (idx & 31)];
    for (int idx = tid; idx < WS0_F; idx += 128)
        ws0[idx] = g_Wxp0[(size_t)(idx >> 5)*Gn + ht*32 + (idx & 31)];

    unsigned long long bias01, bias23;
    {
        float bi = b0v[       ht*8 + u];
        float bf = b0v[ Hn  + ht*8 + u];
        float bg2= b0v[2*Hn + ht*8 + u];
        float bo = b0v[3*Hn + ht*8 + u];
        bias01 = pack2(bi, bf);
        bias23 = pack2(bg2, bo);
    }
    if (ht < 32 && tid < KAn) g_kap[(bt*32 + ht)*KAn + tid] = 0.f;
    float cA = 0.f, cB = 0.f;
    __syncthreads();

    const int rA = (bg*2+0)*516, rB = (bg*2+1)*516;
    const int xA0 = (bg*2+0)*100, xB0 = (bg*2+1)*100;
    const ulonglong2* wv  = (const ulonglong2*)ws;   // idx k*8+u
    const ulonglong2* wv0 = (const ulonglong2*)ws0;

    for (int t = 0; t < Tn; t++) {
        // stage x = [strokes(3) | w_prev(80) | pad0]
        for (int idx = tid; idx < 32*96; idx += 128) {
            int bl = idx / 96, k = idx - bl*96;
            int b = bt*32 + bl;
            float v = 0.f;
            if (k < 3)                 v = strokes[((size_t)b*Tn + t)*3 + k];
            else if (k < 83 && t > 0)  v = g_w[((size_t)(t-1)*Bn + b)*Vn + (k-3)];
            xs[bl*100 + k] = v;
        }
        if (t > 0) {
            const float* hp = &g_h0[((size_t)(t-1)*Bn + bt*32)*Hn];
            for (int idx = tid*4; idx < 32*512; idx += 512) {
                int bl = idx >> 9, k = idx & 511;
                float4 v = *(const float4*)&hp[(size_t)bl*Hn + k];
                *(float4*)&hs[bl*516 + k] = v;
            }
        }
        __syncthreads();

        unsigned long long aA01 = bias01, aA23 = bias23;
        unsigned long long aB01 = bias01, aB23 = bias23;

        // x part (k = 96 padded)
        #pragma unroll 8
        for (int k = 0; k < 96; k++) {
            ulonglong2 w = wv0[k*8 + u];
            unsigned long long xa = pack2(xs[xA0 + k], xs[xA0 + k]);
            unsigned long long xb = pack2(xs[xB0 + k], xs[xB0 + k]);
            fma2(aA01, xa, w.x); fma2(aA23, xa, w.y);
            fma2(aB01, xb, w.x); fma2(aB23, xb, w.y);
        }
        // recurrent part
        if (t > 0) {
            #pragma unroll 8
            for (int k = 0; k < 512; k++) {
                ulonglong2 w = wv[k*8 + u];
                unsigned long long xa = pack2(hs[rA + k], hs[rA + k]);
                unsigned long long xb = pack2(hs[rB + k], hs[rB + k]);
                fma2(aA01, xa, w.x); fma2(aA23, xa, w.y);
                fma2(aB01, xb, w.x); fma2(aB23, xb, w.y);
            }
        }
        // state update
        {
            int b = bt*32 + bg*2;
            float2 if_A = unpk(aA01), goA = unpk(aA23);
            float ig = sigf(if_A.x), fg = sigf(if_A.y), gg = tanhf(goA.x), og = sigf(goA.y);
            cA = fg*cA + ig*gg;
            g_h0[((size_t)t*Bn + b)*Hn + ht*8 + u] = og * tanhf(cA);
            float2 if_B = unpk(aB01), goB = unpk(aB23);
            ig = sigf(if_B.x); fg = sigf(if_B.y); gg = tanhf(goB.x); og = sigf(goB.y);
            cB = fg*cB + ig*gg;
            g_h0[((size_t)t*Bn + b + 1)*Hn + ht*8 + u] = og * tanhf(cB);
        }
        grid_bar(bt);                         // h0[t] done for this b-tile

        if (ht < 32)
            attn_step(t, bt*32 + ht, W_att, b_att, chars, cmask, hs);
        grid_bar(bt);                         // w[t] done for this b-tile
    }
}

// -------------------- persistent scan: layers 1/2 ---------------------------
__global__ __launch_bounds__(128, 1)
void k_scan12(int layer)
{
    extern __shared__ float sm[];
    float* ws = sm;              // [k][32]
    float* hs = sm + WS_F;       // [32][516]

    const float* whp  = (layer == 1) ? g_Whp1 : g_Whp2;
    float*       hseq = (layer == 1) ? g_h1   : g_h2;

    const int bt  = blockIdx.x >> 6;
    const int ht  = blockIdx.x & 63;
    const int tid = threadIdx.x;
    const int u   = tid & 7;
    const int bg  = tid >> 3;

    for (int idx = tid; idx < WS_F; idx += 128)
        ws[idx] = whp[(size_t)(idx >> 5)*Gn + ht*32 + (idx & 31)];
    float cA = 0.f, cB = 0.f;
    __syncthreads();

    const int rA = (bg*2+0)*516, rB = (bg*2+1)*516;
    const ulonglong2* wv = (const ulonglong2*)ws;

    for (int t = 0; t < Tn; t++) {
        const float* pp = &g_pre[(size_t)t*Bn*Gn];
        int bA = bt*32 + bg*2, bB = bA + 1;
        unsigned long long aA01 = pack2(pp[(size_t)bA*Gn +        ht*8 + u],
                                        pp[(size_t)bA*Gn + 512  + ht*8 + u]);
        unsigned long long aA23 = pack2(pp[(size_t)bA*Gn + 1024 + ht*8 + u],
                                        pp[(size_t)bA*Gn + 1536 + ht*8 + u]);
        unsigned long long aB01 = pack2(pp[(size_t)bB*Gn +        ht*8 + u],
                                        pp[(size_t)bB*Gn + 512  + ht*8 + u]);
        unsigned long long aB23 = pack2(pp[(size_t)bB*Gn + 1024 + ht*8 + u],
                                        pp[(size_t)bB*Gn + 1536 + ht*8 + u]);

        if (t > 0) {
            const float* hp = &hseq[((size_t)(t-1)*Bn + bt*32)*Hn];
            for (int idx = tid*4; idx < 32*512; idx += 512) {
                int bl = idx >> 9, k = idx & 511;
                float4 v = *(const float4*)&hp[(size_t)bl*Hn + k];
                *(float4*)&hs[bl*516 + k] = v;
            }
        }
        __syncthreads();

        if (t > 0) {
            #pragma unroll 8
            for (int k = 0; k < 512; k++) {
                ulonglong2 w = wv[k*8 + u];
                unsigned long long xa = pack2(hs[rA + k], hs[rA + k]);
                unsigned long long xb = pack2(hs[rB + k], hs[rB + k]);
                fma2(aA01, xa, w.x); fma2(aA23, xa, w.y);
                fma2(aB01, xb, w.x); fma2(aB23, xb, w.y);
            }
        }
        {
            float2 if_A = unpk(aA01), goA = unpk(aA23);
            float ig = sigf(if_A.x), fg = sigf(if_A.y), gg = tanhf(goA.x), og = sigf(goA.y);
            cA = fg*cA + ig*gg;
            hseq[((size_t)t*Bn + bA)*Hn + ht*8 + u] = og * tanhf(cA);
            float2 if_B = unpk(aB01), goB = unpk(aB23);
            ig = sigf(if_B.x); fg = sigf(if_B.y); gg = tanhf(goB.x); og = sigf(goB.y);
            cB = fg*cB + ig*gg;
            hseq[((size_t)t*Bn + bB)*Hn + ht*8 + u] = og * tanhf(cB);
        }
        grid_bar(bt);
    }
}

// -------------------- cat fill ------------------------------------------------
__global__ void k_fill_cat0(const float* __restrict__ strokes)
{
    size_t idx = (size_t)blockIdx.x * 256 + threadIdx.x;  // over T*B*608
    if (idx >= (size_t)Tn*Bn*K1P) return;
    int k = (int)(idx % K1P);
    size_t n = idx / K1P;
    int t = (int)(n >> 6), b = (int)(n & 63);
    float v = 0.f;
    if (k < 3)        v = strokes[((size_t)b*Tn + t)*3 + k];
    else if (k < 83)  v = g_w[n*Vn + (k-3)];
    else if (k < 595) v = g_h0[n*Hn + (k-83)];
    g_cat[idx] = v;
}

__global__ void k_fill_cat_h1()
{
    size_t idx = (size_t)blockIdx.x * 256 + threadIdx.x;  // over T*B*512
    if (idx >= (size_t)Tn*Bn*Hn) return;
    size_t n = idx >> 9;
    int k = (int)(idx & 511);
    g_cat[n*K1P + 83 + k] = g_h1[idx];
}

// -------------------- batched GEMM: pre = cat @ Wih^T + b -------------------
__global__ __launch_bounds__(256, 2)
void k_gemm_pre(const float* __restrict__ Wih, const float* __restrict__ bias)
{
    const int n0 = blockIdx.x * 64;
    const int j0 = blockIdx.y * 64;
    const int tid = threadIdx.x;
    const int tm = tid >> 4, tn = tid & 15;
    const int mload = tid >> 2;
    const int kq = (tid & 3) * 4;

    __shared__ float As[16][68];
    __shared__ float Bs[16][68];

    unsigned long long acc2[4][2];
    #pragma unroll
    for (int i = 0; i < 4; i++) { acc2[i][0] = 0ull; acc2[i][1] = 0ull; }

    for (int k0 = 0; k0 < K1P; k0 += 16) {
        float4 av = *(const float4*)&g_cat[(size_t)(n0+mload)*K1P + k0 + kq];
        As[kq+0][mload] = av.x; As[kq+1][mload] = av.y;
        As[kq+2][mload] = av.z; As[kq+3][mload] = av.w;

        const float* bptr = &Wih[(size_t)(j0+mload)*K1 + k0 + kq];
        #pragma unroll
        for (int i = 0; i < 4; i++) {
            int k = k0 + kq + i;
            Bs[kq+i][mload] = (k < K1) ? bptr[i] : 0.f;
        }
        __syncthreads();
        #pragma unroll
        for (int kk = 0; kk < 16; kk++) {
            float4 a4 = *(const float4*)&As[kk][tm*4];
            ulonglong2 b2 = *(const ulonglong2*)&Bs[kk][tn*4];
            unsigned long long ax;
            ax = pack2(a4.x, a4.x); fma2(acc2[0][0], ax, b2.x); fma2(acc2[0][1], ax, b2.y);
            ax = pack2(a4.y, a4.y); fma2(acc2[1][0], ax, b2.x); fma2(acc2[1][1], ax, b2.y);
            ax = pack2(a4.z, a4.z); fma2(acc2[2][0], ax, b2.x); fma2(acc2[2][1], ax, b2.y);
            ax = pack2(a4.w, a4.w); fma2(acc2[3][0], ax, b2.x); fma2(acc2[3][1], ax, b2.y);
        }
        __syncthreads();
    }

    #pragma unroll
    for (int i = 0; i < 4; i++) {
        int n = n0 + tm*4 + i;
        float* cp = &g_pre[(size_t)n*Gn + j0 + tn*4];
        float2 c01 = unpk(acc2[i][0]);
        float2 c23 = unpk(acc2[i][1]);
        cp[0] = c01.x + bias[j0 + tn*4 + 0];
        cp[1] = c01.y + bias[j0 + tn*4 + 1];
        cp[2] = c23.x + bias[j0 + tn*4 + 2];
        cp[3] = c23.y + bias[j0 + tn*4 + 3];
    }
}

// -------------------- FC GEMM: fcraw = [h0|h1|h2] @ Wfc^T + b ---------------
__global__ __launch_bounds__(256, 2)
void k_gemm_fc(const float* __restrict__ Wfc, const float* __restrict__ bfc)
{
    const int n0 = blockIdx.x * 64;
    const int j0 = blockIdx.y * 64;
    const int tid = threadIdx.x;
    const int tm = tid >> 4, tn = tid & 15;
    const int mload = tid >> 2;
    const int kq = (tid & 3) * 4;

    __shared__ float As[16][68];
    __shared__ float Bs[16][68];

    unsigned long long acc2[4][2];
    #pragma unroll
    for (int i = 0; i < 4; i++) { acc2[i][0] = 0ull; acc2[i][1] = 0ull; }

    for (int k0 = 0; k0 < FCK; k0 += 16) {
        const float* hsrc = (k0 < 512) ? g_h0 : (k0 < 1024) ? g_h1 : g_h2;
        int krel = (k0 & 511) + kq;
        float4 av = *(const float4*)&hsrc[(size_t)(n0+mload)*Hn + krel];
        As[kq+0][mload] = av.x; As[kq+1][mload] = av.y;
        As[kq+2][mload] = av.z; As[kq+3][mload] = av.w;

        int row = j0 + mload;
        if (row < OUTC) {
            const float* bptr = &Wfc[(size_t)row*FCK + k0 + kq];
            Bs[kq+0][mload] = bptr[0]; Bs[kq+1][mload] = bptr[1];
            Bs[kq+2][mload] = bptr[2]; Bs[kq+3][mload] = bptr[3];
        } else {
            Bs[kq+0][mload] = 0.f; Bs[kq+1][mload] = 0.f;
            Bs[kq+2][mload] = 0.f; Bs[kq+3][mload] = 0.f;
        }
        __syncthreads();
        #pragma unroll
        for (int kk = 0; kk < 16; kk++) {
            float4 a4 = *(const float4*)&As[kk][tm*4];
            ulonglong2 b2 = *(const ulonglong2*)&Bs[kk][tn*4];
            unsigned long long ax;
            ax = pack2(a4.x, a4.x); fma2(acc2[0][0], ax, b2.x); fma2(acc2[0][1], ax, b2.y);
            ax = pack2(a4.y, a4.y); fma2(acc2[1][0], ax, b2.x); fma2(acc2[1][1], ax, b2.y);
            ax = pack2(a4.z, a4.z); fma2(acc2[2][0], ax, b2.x); fma2(acc2[2][1], ax, b2.y);
            ax = pack2(a4.w, a4.w); fma2(acc2[3][0], ax, b2.x); fma2(acc2[3][1], ax, b2.y);
        }
        __syncthreads();
    }

    #pragma unroll
    for (int i = 0; i < 4; i++) {
        int n = n0 + tm*4 + i;
        float2 c01 = unpk(acc2[i][0]);
        float2 c23 = unpk(acc2[i][1]);
        float cv[4] = {c01.x, c01.y, c23.x, c23.y};
        #pragma unroll
        for (int jj = 0; jj < 4; jj++) {
            int jcol = j0 + tn*4 + jj;
            if (jcol < OUTC)
                g_fcraw[(size_t)n*OUTC + jcol] = cv[jj] + bfc[jcol];
        }
    }
}

// -------------------- epilogue ------------------------------------------------
__global__ void k_epilogue(float* __restrict__ out)
{
    int n = blockIdx.x * 128 + threadIdx.x;
    if (n >= Tn*Bn) return;
    const float* r = &g_fcraw[(size_t)n*OUTC];
    int t = n >> 6, b = n & 63;
    float* o = &out[((size_t)b*Tn + t)*OUTC];

    float mx = -1e30f;
    #pragma unroll
    for (int k = 0; k < 20; k++) mx = fmaxf(mx, r[80 + k]);
    float se = 0.f;
    #pragma unroll
    for (int k = 0; k < 20; k++) se += expf(r[80 + k] - mx);
    float lse = mx + logf(se);
    #pragma unroll
    for (int k = 0; k < 20; k++) o[k] = r[80 + k] - lse;          // log_pi
    #pragma unroll
    for (int k = 0; k < 40; k++) o[20 + k] = r[k];                // mu
    #pragma unroll
    for (int k = 0; k < 40; k++) o[60 + k] = r[40 + k];           // log_sigma
    #pragma unroll
    for (int k = 0; k < 20; k++) o[100 + k] = tanhf(r[100 + k]);  // rho
    o[120] = 1.f / (1.f + expf(r[120]));                          // sigmoid(-eos)
}

// -------------------- host launch ---------------------------------------------
extern "C" void kernel_launch(void* const* d_in, const int* in_sizes, int n_in,
                              void* d_out, int out_size)
{
    const int*   chars   = (const int*)  d_in[0];
    const float* cmask   = (const float*)d_in[1];
    const float* strokes = (const float*)d_in[2];
    // d_in[3] strokes_mask unused by reference
    const float* W_ih0   = (const float*)d_in[4];
    const float* W_hh0   = (const float*)d_in[5];
    const float* b0      = (const float*)d_in[6];
    const float* W_att   = (const float*)d_in[7];
    const float* b_att   = (const float*)d_in[8];
    const float* W_ih1   = (const float*)d_in[9];
    const float* W_hh1   = (const float*)d_in[10];
    const float* b1      = (const float*)d_in[11];
    const float* W_ih2   = (const float*)d_in[12];
    const float* W_hh2   = (const float*)d_in[13];
    const float* b2      = (const float*)d_in[14];
    const float* W_fc    = (const float*)d_in[15];
    const float* b_fc    = (const float*)d_in[16];
    float* out = (float*)d_out;

    const int SM0  = (WS_F + WS0_F + XS_F + HS_F) * 4;   // 156,672 B
    const int SM12 = (WS_F + HS_F) * 4;                  // 131,584 B
    cudaFuncSetAttribute(k_scan0,  cudaFuncAttributeMaxDynamicSharedMemorySize, SM0);
    cudaFuncSetAttribute(k_scan12, cudaFuncAttributeMaxDynamicSharedMemorySize, SM12);

    // prep: packed weight layouts
    k_prep_whh<<<(Hn*Gn + 255)/256, 256>>>(W_hh0, 0);
    k_prep_whh<<<(Hn*Gn + 255)/256, 256>>>(W_hh1, 1);
    k_prep_whh<<<(Hn*Gn + 255)/256, 256>>>(W_hh2, 2);
    k_prep_wx0<<<(96*Gn + 255)/256, 256>>>(W_ih0);

    // layer 0 scan (lstm0 + attention), persistent
    k_scan0<<<128, 128, SM0>>>(strokes, b0, W_att, b_att, chars, cmask);

    // layer 1
    {
        size_t tot = (size_t)Tn*Bn*K1P;
        k_fill_cat0<<<(unsigned)((tot + 255)/256), 256>>>(strokes);
    }
    k_gemm_pre<<<dim3(Tn*Bn/64, Gn/64), 256>>>(W_ih1, b1);
    k_scan12<<<128, 128, SM12>>>(1);

    // layer 2
    {
        size_t tot = (size_t)Tn*Bn*Hn;
        k_fill_cat_h1<<<(unsigned)((tot + 255)/256), 256>>>();
    }
    k_gemm_pre<<<dim3(Tn*Bn/64, Gn/64), 256>>>(W_ih2, b2);
    k_scan12<<<128, 128, SM12>>>(2);

    // head
    k_gemm_fc<<<dim3(Tn*Bn/64, 2), 256>>>(W_fc, b_fc);
    k_epilogue<<<(Tn*Bn + 127)/128, 128>>>(out);
}